// round 1
// baseline (speedup 1.0000x reference)
#include <cuda_runtime.h>

// CapsuleLayer: conv(stride2,pad1, 32ic->512oc) per (n,t0) image, then 3 rounds
// of dynamic routing (maxpool(b) -> softmax over t1 -> weighted sum over t0 ->
// squash -> agreement update).
//
// Shapes: x[8,8,32,64,64], W[512,32,3,3], bias[512] -> v[8,8,64,32,32] (fp32)

#define NB   8
#define T0_  8
#define Z0_  32
#define HIN  64
#define WIN  64
#define OC_  512       // T1*Z1
#define T1_  8
#define Z1_  64
#define H1_  32
#define W1_  32
#define KDIM 288       // 32 ic * 9 taps
#define NPIX (H1_*W1_) // 1024

// ---- device scratch (allocation-free rule: __device__ globals) ----
__device__ float g_uhat[NB*NPIX*T0_*OC_];   // [n][hw][t0][oc]  (134 MB)
__device__ float g_wt[KDIM*OC_];            // weights transposed [k][oc]
__device__ float g_b [NB*T0_*T1_*NPIX];     // routing logits [c=n*64+t0*8+t1][hw]
__device__ float g_bp[NB*T0_*T1_*NPIX];     // maxpooled logits

// ---- packed fp32x2 helpers (Blackwell 2x fp32 path, PTX-only) ----
__device__ __forceinline__ unsigned long long pack2(float a, float b) {
    unsigned long long r;
    asm("mov.b64 %0, {%1,%2};" : "=l"(r) : "f"(a), "f"(b));
    return r;
}
__device__ __forceinline__ void fma2(unsigned long long& d,
                                     unsigned long long a, unsigned long long b) {
    asm("fma.rn.f32x2 %0, %1, %2, %0;" : "+l"(d) : "l"(a), "l"(b));
}
__device__ __forceinline__ float2 unpack2(unsigned long long v) {
    float2 r;
    asm("mov.b64 {%0,%1}, %2;" : "=f"(r.x), "=f"(r.y) : "l"(v));
    return r;
}

// ---- weight transpose: W[oc][k] -> g_wt[k][oc] (one-shot, tiny) ----
__global__ void wtrans_kernel(const float* __restrict__ W) {
    int idx = blockIdx.x * 256 + threadIdx.x;
    if (idx < KDIM * OC_) {
        int k  = idx >> 9;      // /512
        int oc = idx & 511;
        g_wt[idx] = W[oc * KDIM + k];
    }
}

// ---- conv: block = (ocg 128-oc chunk, oh row, img). 128 threads.
// thread tile: 4 ow x 8 oc (as 4 f32x2 pairs), oc pairs strided by 32 for
// conflict-free SMEM weight reads.
__global__ __launch_bounds__(128) void conv_kernel(const float* __restrict__ x,
                                                   const float* __restrict__ bias) {
    const int ocg = blockIdx.x;    // 0..3
    const int oh  = blockIdx.y;    // 0..31
    const int img = blockIdx.z;    // 0..63 = n*8 + t0
    const int tid   = threadIdx.x;
    const int ocg16 = tid & 15;    // 16 oc groups
    const int owg   = tid >> 4;    // 8 ow groups
    const int ow0   = owg * 4;

    __shared__ float sIn[8][3][66];     // [ic in chunk][kh row][col+1]
    __shared__ float sW[72][128];       // [k within chunk][oc within 128]

    unsigned long long acc[4][4];       // [owi][j] ; oc pair = 32*j + 2*ocg16
    #pragma unroll
    for (int a = 0; a < 4; ++a)
        #pragma unroll
        for (int b = 0; b < 4; ++b) acc[a][b] = 0ull;

    for (int icc = 0; icc < 4; ++icc) {
        __syncthreads();
        // stage input rows 2*oh-1+kh for 8 input channels (cols padded by 1)
        for (int idx = tid; idx < 8 * 3 * 66; idx += 128) {
            int i   = idx / 198;
            int rem = idx - i * 198;
            int kh  = rem / 66;
            int c   = rem - kh * 66;
            int irow = 2 * oh - 1 + kh;
            int icol = c - 1;
            float v = 0.f;
            if (irow >= 0 && irow < HIN && icol >= 0 && icol < WIN)
                v = x[(img * Z0_ + (icc * 8 + i)) * (HIN * WIN) + irow * WIN + icol];
            sIn[i][kh][c] = v;
        }
        // stage weights (coalesced from transposed layout)
        for (int idx = tid; idx < 72 * 128; idx += 128) {
            int k  = idx >> 7;
            int oc = idx & 127;
            sW[k][oc] = g_wt[(icc * 72 + k) * OC_ + ocg * 128 + oc];
        }
        __syncthreads();

        #pragma unroll
        for (int i = 0; i < 8; ++i) {
            #pragma unroll
            for (int kh = 0; kh < 3; ++kh) {
                unsigned long long a2[9];
                #pragma unroll
                for (int c = 0; c < 9; ++c) {
                    float a = sIn[i][kh][2 * ow0 + c];
                    a2[c] = pack2(a, a);
                }
                #pragma unroll
                for (int kw = 0; kw < 3; ++kw) {
                    int k = i * 9 + kh * 3 + kw;
                    #pragma unroll
                    for (int j = 0; j < 4; ++j) {
                        unsigned long long w2 =
                            *(const unsigned long long*)&sW[k][32 * j + 2 * ocg16];
                        #pragma unroll
                        for (int owi = 0; owi < 4; ++owi)
                            fma2(acc[owi][j], a2[2 * owi + kw], w2);
                    }
                }
            }
        }
    }

    // epilogue: + bias, store to pixel-major u_hat
    const int n  = img >> 3;
    const int t0 = img & 7;
    #pragma unroll
    for (int j = 0; j < 4; ++j) {
        int goc = ocg * 128 + 32 * j + 2 * ocg16;
        float2 bb = *(const float2*)&bias[goc];
        #pragma unroll
        for (int owi = 0; owi < 4; ++owi) {
            float2 v = unpack2(acc[owi][j]);
            v.x += bb.x;
            v.y += bb.y;
            int ow = ow0 + owi;
            int base = ((n * NPIX + oh * W1_ + ow) * T0_ + t0) * OC_ + goc;
            *(float2*)&g_uhat[base] = v;
        }
    }
}

// ---- 3x3 maxpool (stride 1, pad with -inf semantics) on b logits ----
__global__ void pool_kernel() {
    int idx = blockIdx.x * 256 + threadIdx.x;
    if (idx >= NB * T0_ * T1_ * NPIX) return;
    int c  = idx >> 10;
    int hw = idx & 1023;
    int h = hw >> 5, w = hw & 31;
    float m = -3.402823466e38f;
    #pragma unroll
    for (int dh = -1; dh <= 1; ++dh) {
        int hh = h + dh;
        if (hh < 0 || hh >= H1_) continue;
        #pragma unroll
        for (int dw = -1; dw <= 1; ++dw) {
            int ww = w + dw;
            if (ww < 0 || ww >= W1_) continue;
            m = fmaxf(m, g_b[c * NPIX + hh * W1_ + ww]);
        }
    }
    g_bp[idx] = m;
}

// ---- one routing iteration: block per (n, pixel). u_hat slice cached in SMEM.
// iter==0: r uniform (b=0). iter==2: write final v.
__global__ __launch_bounds__(256) void route_kernel(float* __restrict__ out, int iter) {
    __shared__ float su[T0_ * T1_ * Z1_];  // 4096 = 16KB
    __shared__ float sb[64];
    __shared__ float sr[64];
    __shared__ float sp[512];
    __shared__ float sv[512];
    __shared__ float sn2[8];

    const int pix = blockIdx.x;        // 0..8191
    const int n   = pix >> 10;
    const int hw  = pix & 1023;
    const int tid = threadIdx.x;

    const float* ub = g_uhat + (size_t)pix * 4096;
    #pragma unroll
    for (int i = 0; i < 16; ++i) su[tid + 256 * i] = ub[tid + 256 * i];

    if (tid < 64)
        sb[tid] = (iter == 0) ? 0.f : g_bp[(n * 64 + tid) * NPIX + hw];
    __syncthreads();

    if (tid < 8) {  // softmax over t1 for t0 = tid
        float m = -1e30f;
        #pragma unroll
        for (int t = 0; t < 8; ++t) m = fmaxf(m, sb[tid * 8 + t]);
        float e[8], s = 0.f;
        #pragma unroll
        for (int t = 0; t < 8; ++t) { e[t] = expf(sb[tid * 8 + t] - m); s += e[t]; }
        float inv = 1.f / s;
        #pragma unroll
        for (int t = 0; t < 8; ++t) sr[tid * 8 + t] = e[t] * inv;
    }
    __syncthreads();

    // p[t1][z] = sum_t0 r[t0][t1] * u[t0][t1][z] ; each thread does 2 elems
    const int t1a = tid >> 6;        // 0..3
    const int za  = tid & 63;
    const int t1b = t1a + 4;
    float p0 = 0.f, p1 = 0.f;
    #pragma unroll
    for (int t0 = 0; t0 < 8; ++t0) {
        p0 += sr[t0 * 8 + t1a] * su[(t0 * 8 + t1a) * 64 + za];
        p1 += sr[t0 * 8 + t1b] * su[(t0 * 8 + t1b) * 64 + za];
    }
    sp[tid] = p0;
    sp[tid + 256] = p1;
    __syncthreads();

    if (tid < 8) {  // squared norm per t1
        float s = 0.f;
        #pragma unroll
        for (int z = 0; z < 64; ++z) { float q = sp[tid * 64 + z]; s += q * q; }
        sn2[tid] = s;
    }
    __syncthreads();

    float na = sn2[t1a];
    float fa = na / ((1.f + na) * sqrtf(na + 1e-9f));
    float nb = sn2[t1b];
    float fb = nb / ((1.f + nb) * sqrtf(nb + 1e-9f));
    float v0 = p0 * fa;
    float v1 = p1 * fb;
    sv[tid] = v0;
    sv[tid + 256] = v1;

    if (iter == 2) {
        out[((n * 8 + t1a) * 64 + za) * NPIX + hw] = v0;
        out[((n * 8 + t1b) * 64 + za) * NPIX + hw] = v1;
        return;
    }
    __syncthreads();

    if (tid < 64) {  // agreement: b += sum_z u[t0][t1][z] * v[t1][z]
        int t1 = tid & 7;
        float d = 0.f;
        #pragma unroll
        for (int zz = 0; zz < 64; ++zz) {
            int z = (zz + tid) & 63;  // stagger to avoid bank conflicts
            d += su[tid * 64 + z] * sv[t1 * 64 + z];
        }
        float bold = (iter == 0) ? 0.f : g_b[(n * 64 + tid) * NPIX + hw];
        g_b[(n * 64 + tid) * NPIX + hw] = bold + d;
    }
}

extern "C" void kernel_launch(void* const* d_in, const int* in_sizes, int n_in,
                              void* d_out, int out_size) {
    const float* x    = (const float*)d_in[0];
    const float* W    = (const float*)d_in[1];
    const float* bias = (const float*)d_in[2];
    float* out = (float*)d_out;

    wtrans_kernel<<<(KDIM * OC_ + 255) / 256, 256>>>(W);
    conv_kernel<<<dim3(4, H1_, NB * T0_), 128>>>(x, bias);
    route_kernel<<<NB * NPIX, 256>>>(out, 0);
    pool_kernel<<<(NB * T0_ * T1_ * NPIX + 255) / 256, 256>>>();
    route_kernel<<<NB * NPIX, 256>>>(out, 1);
    pool_kernel<<<(NB * T0_ * T1_ * NPIX + 255) / 256, 256>>>();
    route_kernel<<<NB * NPIX, 256>>>(out, 2);
}

// round 3
// speedup vs baseline: 1.8646x; 1.8646x over previous
#include <cuda_runtime.h>
#include <cuda_bf16.h>
#include <cstdint>

// CapsuleLayer: conv(stride2,pad1, 32ic->512oc) per (n,t0) image via mma.sync
// bf16-split implicit GEMM (3-term fp32 emulation), then 3 routing rounds.
// Shapes: x[8,8,32,64,64], W[512,32,3,3], bias[512] -> v[8,8,64,32,32] (fp32)

#define NB   8
#define T0_  8
#define Z0_  32
#define HIN  64
#define WIN  64
#define OC_  512
#define T1_  8
#define Z1_  64
#define H1_  32
#define W1_  32
#define NPIX (H1_*W1_)      // 1024
#define KTOT 288            // 9 taps * 32 ic
#define NIMG 64

// ---- device scratch ----
__device__ float         g_uhat[NB*NPIX*T0_*OC_];     // [n][hw][t0][oc]
__device__ __nv_bfloat16 g_xhi[NIMG*HIN*WIN*Z0_];     // [img][h][w][ic]
__device__ __nv_bfloat16 g_xlo[NIMG*HIN*WIN*Z0_];
__device__ __nv_bfloat16 g_whi[OC_*KTOT];             // [oc][tap*32+ic]
__device__ __nv_bfloat16 g_wlo[OC_*KTOT];
__device__ float         g_b [NB*T0_*T1_*NPIX];
__device__ float         g_bp[NB*T0_*T1_*NPIX];

__device__ __forceinline__ uint32_t smem_u32(const void* p) {
    uint32_t a;
    asm("{ .reg .u64 t; cvta.to.shared.u64 t, %1; cvt.u32.u64 %0, t; }"
        : "=r"(a) : "l"(p));
    return a;
}
__device__ __forceinline__ void ldm_x4(uint32_t* r, uint32_t addr) {
    asm volatile("ldmatrix.sync.aligned.m8n8.x4.shared.b16 {%0,%1,%2,%3}, [%4];"
                 : "=r"(r[0]), "=r"(r[1]), "=r"(r[2]), "=r"(r[3]) : "r"(addr));
}
__device__ __forceinline__ void mma16816(float* d, const uint32_t* a,
                                         uint32_t b0, uint32_t b1) {
    asm volatile(
        "mma.sync.aligned.m16n8k16.row.col.f32.bf16.bf16.f32 "
        "{%0,%1,%2,%3}, {%4,%5,%6,%7}, {%8,%9}, {%0,%1,%2,%3};"
        : "+f"(d[0]), "+f"(d[1]), "+f"(d[2]), "+f"(d[3])
        : "r"(a[0]), "r"(a[1]), "r"(a[2]), "r"(a[3]), "r"(b0), "r"(b1));
}

// ========================= prep: split x / W into bf16 hi+lo ================
__global__ __launch_bounds__(256) void xsplit_kernel(const float* __restrict__ x) {
    __shared__ float t[32][65];
    const int img = blockIdx.x;
    const int h   = blockIdx.y;
    const int tid = threadIdx.x;
    #pragma unroll
    for (int j = 0; j < 8; ++j) {
        int idx = tid + 256 * j;
        int ic = idx >> 6, w = idx & 63;
        t[ic][w] = x[((img * Z0_ + ic) * HIN + h) * WIN + w];
    }
    __syncthreads();
    #pragma unroll
    for (int j = 0; j < 8; ++j) {
        int idx = tid + 256 * j;
        int w = idx >> 5, ic = idx & 31;
        float v = t[ic][w];
        __nv_bfloat16 hi = __float2bfloat16(v);
        float r = v - __bfloat162float(hi);
        int o = ((img * HIN + h) * WIN + w) * Z0_ + ic;
        g_xhi[o] = hi;
        g_xlo[o] = __float2bfloat16(r);
    }
}

__global__ void wsplit_kernel(const float* __restrict__ W) {
    int idx = blockIdx.x * 256 + threadIdx.x;
    if (idx >= OC_ * KTOT) return;
    int oc = idx / KTOT;
    int k  = idx - oc * KTOT;
    int tap = k >> 5, ic = k & 31;
    float v = W[oc * KTOT + ic * 9 + tap];
    __nv_bfloat16 hi = __float2bfloat16(v);
    float r = v - __bfloat162float(hi);
    g_whi[idx] = hi;
    g_wlo[idx] = __float2bfloat16(r);
}

// ========================= conv: mma.sync implicit GEMM =====================
// CTA = 128 px x 128 oc of one image; 8 warps = 4(m) x 2(n); warp = 32px x 64oc.
// K = 9 chunks of 32 (1 tap x 32 ic). A/B staged per chunk with 80B row pitch
// (64B data + 16B pad -> ldmatrix conflict-free).
#define APITCH 80
#define ASTG   (128 * APITCH)      // 10240 B per operand

__global__ __launch_bounds__(256, 2) void conv_mma_kernel(const float* __restrict__ bias) {
    __shared__ char sAhi[ASTG], sAlo[ASTG], sBhi[ASTG], sBlo[ASTG];

    const int tid  = threadIdx.x;
    const int lid  = tid & 31;
    const int wid  = tid >> 5;
    const int mblk = blockIdx.x;   // 0..7 (128-pixel slab)
    const int nblk = blockIdx.y;   // 0..3 (128-oc slab)
    const int img  = blockIdx.z;   // 0..63

    const int warp_m = wid & 3;        // 4 warps over pixels
    const int warp_n = wid >> 2;       // 2 warps over oc
    const int wPx = warp_m * 32;
    const int wOc = warp_n * 64;

    // staging geometry: thread handles half a row (32B) of A and of B
    const int p_loc = tid >> 1;
    const int half  = tid & 1;
    const int p     = mblk * 128 + p_loc;
    const int oh = p >> 5, ow = p & 31;
    const __nv_bfloat16* wsrcH = g_whi + (size_t)(nblk * 128 + p_loc) * KTOT;
    const __nv_bfloat16* wsrcL = g_wlo + (size_t)(nblk * 128 + p_loc) * KTOT;

    const uint32_t aHiB = smem_u32(sAhi);
    const uint32_t aLoB = smem_u32(sAlo);
    const uint32_t bHiB = smem_u32(sBhi);
    const uint32_t bLoB = smem_u32(sBlo);

    // ldmatrix per-lane address components
    const uint32_t aRow  = ((lid >> 3) & 1) * 8 + (lid & 7);    // row within m16
    const uint32_t aKoff = (lid >> 4) * 16;                     // k8 byte offset
    const uint32_t aLane = (wPx + aRow) * APITCH + aKoff;
    const uint32_t bRow  = (lid >> 4) * 8 + (lid & 7);          // n within n16
    const uint32_t bKoff = ((lid >> 3) & 1) * 16;
    const uint32_t bLane = (wOc + bRow) * APITCH + bKoff;

    float acc[2][8][4];
    #pragma unroll
    for (int i = 0; i < 2; ++i)
        #pragma unroll
        for (int j = 0; j < 8; ++j)
            #pragma unroll
            for (int q = 0; q < 4; ++q) acc[i][j][q] = 0.f;

    for (int c = 0; c < 9; ++c) {
        __syncthreads();
        // ---- stage A: 64B of im2col row per pixel (hi+lo), split across 2 thr
        {
            int kh = c / 3, kw = c - 3 * kh;
            int ih = 2 * oh - 1 + kh, iw = 2 * ow - 1 + kw;
            bool valid = (ih >= 0) && (ih < HIN) && (iw >= 0) && (iw < WIN);
            size_t so = ((size_t)(img * (HIN * WIN) + ih * WIN + iw)) * Z0_ + half * 16;
            uint4 z; z.x = z.y = z.z = z.w = 0u;
            uint4 h0 = valid ? *(const uint4*)(g_xhi + so)     : z;
            uint4 h1 = valid ? *(const uint4*)(g_xhi + so + 8) : z;
            uint4 l0 = valid ? *(const uint4*)(g_xlo + so)     : z;
            uint4 l1 = valid ? *(const uint4*)(g_xlo + so + 8) : z;
            int d = p_loc * APITCH + half * 32;
            *(uint4*)(sAhi + d)      = h0;
            *(uint4*)(sAhi + d + 16) = h1;
            *(uint4*)(sAlo + d)      = l0;
            *(uint4*)(sAlo + d + 16) = l1;
        }
        // ---- stage B: 64B of weights per oc row (hi+lo)
        {
            size_t so = (size_t)c * 32 + half * 16;
            uint4 h0 = *(const uint4*)(wsrcH + so);
            uint4 h1 = *(const uint4*)(wsrcH + so + 8);
            uint4 l0 = *(const uint4*)(wsrcL + so);
            uint4 l1 = *(const uint4*)(wsrcL + so + 8);
            int d = p_loc * APITCH + half * 32;
            *(uint4*)(sBhi + d)      = h0;
            *(uint4*)(sBhi + d + 16) = h1;
            *(uint4*)(sBlo + d)      = l0;
            *(uint4*)(sBlo + d + 16) = l1;
        }
        __syncthreads();

        #pragma unroll
        for (int ks = 0; ks < 2; ++ks) {
            uint32_t Ahi[2][4], Alo[2][4];
            #pragma unroll
            for (int i = 0; i < 2; ++i) {
                uint32_t off = i * (16 * APITCH) + ks * 32 + aLane;
                ldm_x4(Ahi[i], aHiB + off);
                ldm_x4(Alo[i], aLoB + off);
            }
            #pragma unroll
            for (int j = 0; j < 4; ++j) {           // 4 n16 groups
                uint32_t off = j * (16 * APITCH) + ks * 32 + bLane;
                uint32_t Bhi[4], Blo[4];
                ldm_x4(Bhi, bHiB + off);
                ldm_x4(Blo, bLoB + off);
                #pragma unroll
                for (int i = 0; i < 2; ++i) {
                    mma16816(acc[i][2 * j],     Ahi[i], Bhi[0], Bhi[1]);
                    mma16816(acc[i][2 * j + 1], Ahi[i], Bhi[2], Bhi[3]);
                    mma16816(acc[i][2 * j],     Ahi[i], Blo[0], Blo[1]);
                    mma16816(acc[i][2 * j + 1], Ahi[i], Blo[2], Blo[3]);
                    mma16816(acc[i][2 * j],     Alo[i], Bhi[0], Bhi[1]);
                    mma16816(acc[i][2 * j + 1], Alo[i], Bhi[2], Bhi[3]);
                }
            }
        }
    }

    // ---- epilogue: + bias, write pixel-major u_hat ----
    const int n = img >> 3, t0 = img & 7;
    const int rowBase = mblk * 128 + wPx + (lid >> 2);
    const int ocBase  = nblk * 128 + wOc + 2 * (lid & 3);
    #pragma unroll
    for (int j = 0; j < 8; ++j) {
        int oc = ocBase + j * 8;
        float2 bb = *(const float2*)(bias + oc);
        #pragma unroll
        for (int i = 0; i < 2; ++i) {
            int r0 = rowBase + i * 16;
            float* d0 = g_uhat + ((size_t)((n * NPIX + r0) * T0_ + t0)) * OC_ + oc;
            float* d1 = g_uhat + ((size_t)((n * NPIX + r0 + 8) * T0_ + t0)) * OC_ + oc;
            float2 v0 = make_float2(acc[i][j][0] + bb.x, acc[i][j][1] + bb.y);
            float2 v1 = make_float2(acc[i][j][2] + bb.x, acc[i][j][3] + bb.y);
            *(float2*)d0 = v0;
            *(float2*)d1 = v1;
        }
    }
}

// ========================= routing (unchanged, passing) =====================
__global__ void pool_kernel() {
    int idx = blockIdx.x * 256 + threadIdx.x;
    if (idx >= NB * T0_ * T1_ * NPIX) return;
    int c  = idx >> 10;
    int hw = idx & 1023;
    int h = hw >> 5, w = hw & 31;
    float m = -3.402823466e38f;
    #pragma unroll
    for (int dh = -1; dh <= 1; ++dh) {
        int hh = h + dh;
        if (hh < 0 || hh >= H1_) continue;
        #pragma unroll
        for (int dw = -1; dw <= 1; ++dw) {
            int ww = w + dw;
            if (ww < 0 || ww >= W1_) continue;
            m = fmaxf(m, g_b[c * NPIX + hh * W1_ + ww]);
        }
    }
    g_bp[idx] = m;
}

__global__ __launch_bounds__(256) void route_kernel(float* __restrict__ out, int iter) {
    __shared__ float su[T0_ * T1_ * Z1_];
    __shared__ float sb[64];
    __shared__ float sr[64];
    __shared__ float sp[512];
    __shared__ float sv[512];
    __shared__ float sn2[8];

    const int pix = blockIdx.x;
    const int n   = pix >> 10;
    const int hw  = pix & 1023;
    const int tid = threadIdx.x;

    const float* ub = g_uhat + (size_t)pix * 4096;
    #pragma unroll
    for (int i = 0; i < 16; ++i) su[tid + 256 * i] = ub[tid + 256 * i];

    if (tid < 64)
        sb[tid] = (iter == 0) ? 0.f : g_bp[(n * 64 + tid) * NPIX + hw];
    __syncthreads();

    if (tid < 8) {
        float m = -1e30f;
        #pragma unroll
        for (int t = 0; t < 8; ++t) m = fmaxf(m, sb[tid * 8 + t]);
        float e[8], s = 0.f;
        #pragma unroll
        for (int t = 0; t < 8; ++t) { e[t] = expf(sb[tid * 8 + t] - m); s += e[t]; }
        float inv = 1.f / s;
        #pragma unroll
        for (int t = 0; t < 8; ++t) sr[tid * 8 + t] = e[t] * inv;
    }
    __syncthreads();

    const int t1a = tid >> 6;
    const int za  = tid & 63;
    const int t1b = t1a + 4;
    float p0 = 0.f, p1 = 0.f;
    #pragma unroll
    for (int t0 = 0; t0 < 8; ++t0) {
        p0 += sr[t0 * 8 + t1a] * su[(t0 * 8 + t1a) * 64 + za];
        p1 += sr[t0 * 8 + t1b] * su[(t0 * 8 + t1b) * 64 + za];
    }
    sp[tid] = p0;
    sp[tid + 256] = p1;
    __syncthreads();

    if (tid < 8) {
        float s = 0.f;
        #pragma unroll
        for (int z = 0; z < 64; ++z) { float q = sp[tid * 64 + z]; s += q * q; }
        sn2[tid] = s;
    }
    __syncthreads();

    float na = sn2[t1a];
    float fa = na / ((1.f + na) * sqrtf(na + 1e-9f));
    float nb = sn2[t1b];
    float fb = nb / ((1.f + nb) * sqrtf(nb + 1e-9f));
    float v0 = p0 * fa;
    float v1 = p1 * fb;
    sv[tid] = v0;
    sv[tid + 256] = v1;

    if (iter == 2) {
        out[((n * 8 + t1a) * 64 + za) * NPIX + hw] = v0;
        out[((n * 8 + t1b) * 64 + za) * NPIX + hw] = v1;
        return;
    }
    __syncthreads();

    if (tid < 64) {
        int t1 = tid & 7;
        float d = 0.f;
        #pragma unroll
        for (int zz = 0; zz < 64; ++zz) {
            int z = (zz + tid) & 63;
            d += su[tid * 64 + z] * sv[t1 * 64 + z];
        }
        float bold = (iter == 0) ? 0.f : g_b[(n * 64 + tid) * NPIX + hw];
        g_b[(n * 64 + tid) * NPIX + hw] = bold + d;
    }
}

extern "C" void kernel_launch(void* const* d_in, const int* in_sizes, int n_in,
                              void* d_out, int out_size) {
    const float* x    = (const float*)d_in[0];
    const float* W    = (const float*)d_in[1];
    const float* bias = (const float*)d_in[2];
    float* out = (float*)d_out;

    xsplit_kernel<<<dim3(NIMG, HIN), 256>>>(x);
    wsplit_kernel<<<(OC_ * KTOT + 255) / 256, 256>>>(W);
    conv_mma_kernel<<<dim3(8, 4, NIMG), 256>>>(bias);
    route_kernel<<<NB * NPIX, 256>>>(out, 0);
    pool_kernel<<<(NB * T0_ * T1_ * NPIX + 255) / 256, 256>>>();
    route_kernel<<<NB * NPIX, 256>>>(out, 1);
    pool_kernel<<<(NB * T0_ * T1_ * NPIX + 255) / 256, 256>>>();
    route_kernel<<<NB * NPIX, 256>>>(out, 2);
}

// round 4
// speedup vs baseline: 2.1683x; 1.1629x over previous
#include <cuda_runtime.h>
#include <cuda_bf16.h>
#include <cstdint>

// CapsuleLayer: conv(stride2,pad1, 32ic->512oc) per (n,t0) image via mma.sync
// bf16-split implicit GEMM (3-term fp32 emulation), cp.async double-buffered.
// Then 3 routing rounds (parallelized reductions) + coalesced output transpose.
// Shapes: x[8,8,32,64,64], W[512,32,3,3], bias[512] -> v[8,8,64,32,32] (fp32)

#define NB   8
#define T0_  8
#define Z0_  32
#define HIN  64
#define WIN  64
#define OC_  512
#define H1_  32
#define W1_  32
#define NPIX (H1_*W1_)      // 1024
#define KTOT 288            // 9 taps * 32 ic
#define NIMG 64

// ---- device scratch ----
__device__ float         g_uhat[NB*NPIX*T0_*OC_];     // [n][hw][t0][oc]
__device__ float         g_v[NB*NPIX*OC_];            // [n][hw][t1*64+z]
__device__ __nv_bfloat16 g_xhi[NIMG*HIN*WIN*Z0_];     // [img][h][w][ic]
__device__ __nv_bfloat16 g_xlo[NIMG*HIN*WIN*Z0_];
__device__ __nv_bfloat16 g_whi[OC_*KTOT];             // [oc][tap*32+ic]
__device__ __nv_bfloat16 g_wlo[OC_*KTOT];
__device__ float         g_b [NB*T0_*8*NPIX];
__device__ float         g_bp[NB*T0_*8*NPIX];

__device__ __forceinline__ uint32_t smem_u32(const void* p) {
    uint32_t a;
    asm("{ .reg .u64 t; cvta.to.shared.u64 t, %1; cvt.u32.u64 %0, t; }"
        : "=r"(a) : "l"(p));
    return a;
}
__device__ __forceinline__ void ldm_x4(uint32_t* r, uint32_t addr) {
    asm volatile("ldmatrix.sync.aligned.m8n8.x4.shared.b16 {%0,%1,%2,%3}, [%4];"
                 : "=r"(r[0]), "=r"(r[1]), "=r"(r[2]), "=r"(r[3]) : "r"(addr));
}
__device__ __forceinline__ void mma16816(float* d, const uint32_t* a,
                                         uint32_t b0, uint32_t b1) {
    asm volatile(
        "mma.sync.aligned.m16n8k16.row.col.f32.bf16.bf16.f32 "
        "{%0,%1,%2,%3}, {%4,%5,%6,%7}, {%8,%9}, {%0,%1,%2,%3};"
        : "+f"(d[0]), "+f"(d[1]), "+f"(d[2]), "+f"(d[3])
        : "r"(a[0]), "r"(a[1]), "r"(a[2]), "r"(a[3]), "r"(b0), "r"(b1));
}
__device__ __forceinline__ void cp16(uint32_t d, const void* s, uint32_t n) {
    asm volatile("cp.async.cg.shared.global [%0], [%1], 16, %2;"
                 :: "r"(d), "l"(s), "r"(n) : "memory");
}
__device__ __forceinline__ void cp_commit() {
    asm volatile("cp.async.commit_group;" ::: "memory");
}

// ========================= prep: split x / W into bf16 hi+lo ================
__global__ __launch_bounds__(256) void xsplit_kernel(const float* __restrict__ x) {
    __shared__ float t[32][65];
    const int img = blockIdx.x;
    const int h   = blockIdx.y;
    const int tid = threadIdx.x;
    #pragma unroll
    for (int j = 0; j < 8; ++j) {
        int idx = tid + 256 * j;
        int ic = idx >> 6, w = idx & 63;
        t[ic][w] = x[((img * Z0_ + ic) * HIN + h) * WIN + w];
    }
    __syncthreads();
    #pragma unroll
    for (int j = 0; j < 8; ++j) {
        int idx = tid + 256 * j;
        int w = idx >> 5, ic = idx & 31;
        float v = t[ic][w];
        __nv_bfloat16 hi = __float2bfloat16(v);
        float r = v - __bfloat162float(hi);
        int o = ((img * HIN + h) * WIN + w) * Z0_ + ic;
        g_xhi[o] = hi;
        g_xlo[o] = __float2bfloat16(r);
    }
}

__global__ void wsplit_kernel(const float* __restrict__ W) {
    int idx = blockIdx.x * 256 + threadIdx.x;
    if (idx >= OC_ * KTOT) return;
    int oc = idx / KTOT;
    int k  = idx - oc * KTOT;
    int tap = k >> 5, ic = k & 31;
    float v = W[oc * KTOT + ic * 9 + tap];
    __nv_bfloat16 hi = __float2bfloat16(v);
    float r = v - __bfloat162float(hi);
    g_whi[idx] = hi;
    g_wlo[idx] = __float2bfloat16(r);
}

// ========================= conv: mma.sync implicit GEMM =====================
// CTA = 128 px x 128 oc of one image; 8 warps = 4(m) x 2(n); warp = 32px x 64oc.
// K = 9 chunks of 32 (1 tap x 32 ic), cp.async double-buffered.
#define APITCH  80
#define OPBYTES (128 * APITCH)     // 10240 per operand
#define STGB    (4 * OPBYTES)      // Ahi,Alo,Bhi,Blo
#define SMEMTOT (2 * STGB)         // 81920

__device__ __forceinline__ void stage_chunk(
        int c, uint32_t sbase, uint32_t dA, int oh, int ow,
        const __nv_bfloat16* xhiImg, const __nv_bfloat16* xloImg,
        const __nv_bfloat16* wH, const __nv_bfloat16* wL) {
    int kh = c / 3, kw = c - 3 * kh;
    int ih = 2 * oh - 1 + kh, iw = 2 * ow - 1 + kw;
    bool valid = ((unsigned)ih < (unsigned)HIN) && ((unsigned)iw < (unsigned)WIN);
    uint32_t vb = valid ? 16u : 0u;
    size_t so = valid ? (size_t)(ih * WIN + iw) * Z0_ : 0;
    const char* aH = (const char*)(xhiImg + so);
    const char* aL = (const char*)(xloImg + so);
    cp16(sbase + dA,                   aH,      vb);
    cp16(sbase + dA + 16,              aH + 16, vb);
    cp16(sbase + OPBYTES + dA,         aL,      vb);
    cp16(sbase + OPBYTES + dA + 16,    aL + 16, vb);
    const char* bH = (const char*)(wH + c * 32);
    const char* bL = (const char*)(wL + c * 32);
    cp16(sbase + 2 * OPBYTES + dA,      bH,      16u);
    cp16(sbase + 2 * OPBYTES + dA + 16, bH + 16, 16u);
    cp16(sbase + 3 * OPBYTES + dA,      bL,      16u);
    cp16(sbase + 3 * OPBYTES + dA + 16, bL + 16, 16u);
    cp_commit();
}

__device__ __forceinline__ void compute_chunk(
        uint32_t sbase, uint32_t aLane, uint32_t bLane, float acc[2][8][4]) {
    const uint32_t aHiB = sbase;
    const uint32_t aLoB = sbase + OPBYTES;
    const uint32_t bHiB = sbase + 2 * OPBYTES;
    const uint32_t bLoB = sbase + 3 * OPBYTES;
    #pragma unroll
    for (int ks = 0; ks < 2; ++ks) {
        uint32_t Ahi[2][4], Alo[2][4];
        #pragma unroll
        for (int i = 0; i < 2; ++i) {
            uint32_t off = i * (16 * APITCH) + ks * 32 + aLane;
            ldm_x4(Ahi[i], aHiB + off);
            ldm_x4(Alo[i], aLoB + off);
        }
        #pragma unroll
        for (int j = 0; j < 4; ++j) {
            uint32_t off = j * (16 * APITCH) + ks * 32 + bLane;
            uint32_t Bhi[4], Blo[4];
            ldm_x4(Bhi, bHiB + off);
            ldm_x4(Blo, bLoB + off);
            #pragma unroll
            for (int i = 0; i < 2; ++i) {
                mma16816(acc[i][2 * j],     Ahi[i], Bhi[0], Bhi[1]);
                mma16816(acc[i][2 * j + 1], Ahi[i], Bhi[2], Bhi[3]);
                mma16816(acc[i][2 * j],     Ahi[i], Blo[0], Blo[1]);
                mma16816(acc[i][2 * j + 1], Ahi[i], Blo[2], Blo[3]);
                mma16816(acc[i][2 * j],     Alo[i], Bhi[0], Bhi[1]);
                mma16816(acc[i][2 * j + 1], Alo[i], Bhi[2], Bhi[3]);
            }
        }
    }
}

__global__ __launch_bounds__(256, 2) void conv_mma_kernel(const float* __restrict__ bias) {
    extern __shared__ char smem[];
    const uint32_t base0 = smem_u32(smem);
    const uint32_t base1 = base0 + STGB;

    const int tid  = threadIdx.x;
    const int lid  = tid & 31;
    const int wid  = tid >> 5;
    const int mblk = blockIdx.x;   // 0..7 (128-pixel slab)
    const int nblk = blockIdx.y;   // 0..3 (128-oc slab)
    const int img  = blockIdx.z;   // 0..63

    const int warp_m = wid & 3;
    const int warp_n = wid >> 2;
    const int wPx = warp_m * 32;
    const int wOc = warp_n * 64;

    // staging geometry: thread handles 32B (half row) of A and of B
    const int p_loc = tid >> 1;
    const int half  = tid & 1;
    const int p     = mblk * 128 + p_loc;
    const int oh = p >> 5, ow = p & 31;
    const uint32_t dA = (uint32_t)(p_loc * APITCH + half * 32);
    const __nv_bfloat16* xhiImg = g_xhi + (size_t)img * (HIN * WIN * Z0_) + half * 16;
    const __nv_bfloat16* xloImg = g_xlo + (size_t)img * (HIN * WIN * Z0_) + half * 16;
    const __nv_bfloat16* wH = g_whi + (size_t)(nblk * 128 + p_loc) * KTOT + half * 16;
    const __nv_bfloat16* wL = g_wlo + (size_t)(nblk * 128 + p_loc) * KTOT + half * 16;

    // ldmatrix per-lane address components
    const uint32_t aRow  = ((lid >> 3) & 1) * 8 + (lid & 7);
    const uint32_t aKoff = (lid >> 4) * 16;
    const uint32_t aLane = (wPx + aRow) * APITCH + aKoff;
    const uint32_t bRow  = (lid >> 4) * 8 + (lid & 7);
    const uint32_t bKoff = ((lid >> 3) & 1) * 16;
    const uint32_t bLane = (wOc + bRow) * APITCH + bKoff;

    float acc[2][8][4];
    #pragma unroll
    for (int i = 0; i < 2; ++i)
        #pragma unroll
        for (int j = 0; j < 8; ++j)
            #pragma unroll
            for (int q = 0; q < 4; ++q) acc[i][j][q] = 0.f;

    stage_chunk(0, base0, dA, oh, ow, xhiImg, xloImg, wH, wL);
    stage_chunk(1, base1, dA, oh, ow, xhiImg, xloImg, wH, wL);

    #pragma unroll
    for (int c = 0; c < 9; ++c) {
        if (c < 8) asm volatile("cp.async.wait_group 1;" ::: "memory");
        else       asm volatile("cp.async.wait_group 0;" ::: "memory");
        __syncthreads();
        compute_chunk((c & 1) ? base1 : base0, aLane, bLane, acc);
        if (c + 2 < 9) {
            __syncthreads();
            stage_chunk(c + 2, (c & 1) ? base1 : base0, dA, oh, ow,
                        xhiImg, xloImg, wH, wL);
        }
    }

    // ---- epilogue: + bias, write pixel-major u_hat ----
    const int n = img >> 3, t0 = img & 7;
    const int rowBase = mblk * 128 + wPx + (lid >> 2);
    const int ocBase  = nblk * 128 + wOc + 2 * (lid & 3);
    #pragma unroll
    for (int j = 0; j < 8; ++j) {
        int oc = ocBase + j * 8;
        float2 bb = *(const float2*)(bias + oc);
        #pragma unroll
        for (int i = 0; i < 2; ++i) {
            int r0 = rowBase + i * 16;
            float* d0 = g_uhat + ((size_t)((n * NPIX + r0) * T0_ + t0)) * OC_ + oc;
            float* d1 = g_uhat + ((size_t)((n * NPIX + r0 + 8) * T0_ + t0)) * OC_ + oc;
            *(float2*)d0 = make_float2(acc[i][j][0] + bb.x, acc[i][j][1] + bb.y);
            *(float2*)d1 = make_float2(acc[i][j][2] + bb.x, acc[i][j][3] + bb.y);
        }
    }
}

// ========================= routing ==========================================
__global__ void pool_kernel() {
    int idx = blockIdx.x * 256 + threadIdx.x;
    if (idx >= NB * 64 * NPIX) return;
    int c  = idx >> 10;
    int hw = idx & 1023;
    int h = hw >> 5, w = hw & 31;
    float m = -3.402823466e38f;
    #pragma unroll
    for (int dh = -1; dh <= 1; ++dh) {
        int hh = h + dh;
        if (hh < 0 || hh >= H1_) continue;
        #pragma unroll
        for (int dw = -1; dw <= 1; ++dw) {
            int ww = w + dw;
            if (ww < 0 || ww >= W1_) continue;
            m = fmaxf(m, g_b[c * NPIX + hh * W1_ + ww]);
        }
    }
    g_bp[idx] = m;
}

__global__ __launch_bounds__(256) void route_kernel(int iter) {
    __shared__ __align__(16) float su[4096];
    __shared__ float sb[64], sr[64], sp[512], sv[512], sn2[8];

    const int pix = blockIdx.x;
    const int n   = pix >> 10;
    const int hw  = pix & 1023;
    const int tid = threadIdx.x;

    const float4* ub4 = (const float4*)(g_uhat + (size_t)pix * 4096);
    float4* su4 = (float4*)su;
    #pragma unroll
    for (int i = 0; i < 4; ++i) su4[tid + 256 * i] = ub4[tid + 256 * i];
    if (tid < 64) sb[tid] = (iter == 0) ? 0.f : g_bp[(n * 64 + tid) * NPIX + hw];
    __syncthreads();

    if (tid < 8) {   // softmax over t1 for t0 = tid
        float m = -1e30f;
        #pragma unroll
        for (int t = 0; t < 8; ++t) m = fmaxf(m, sb[tid * 8 + t]);
        float e[8], s = 0.f;
        #pragma unroll
        for (int t = 0; t < 8; ++t) { e[t] = expf(sb[tid * 8 + t] - m); s += e[t]; }
        float inv = 1.f / s;
        #pragma unroll
        for (int t = 0; t < 8; ++t) sr[tid * 8 + t] = e[t] * inv;
    }
    __syncthreads();

    const int t1a = tid >> 6, za = tid & 63, t1b = t1a + 4;
    float ua[8], ubr[8];
    float p0 = 0.f, p1 = 0.f;
    #pragma unroll
    for (int t0 = 0; t0 < 8; ++t0) {
        ua[t0]  = su[(t0 * 8 + t1a) * 64 + za];
        ubr[t0] = su[(t0 * 8 + t1b) * 64 + za];
        p0 += sr[t0 * 8 + t1a] * ua[t0];
        p1 += sr[t0 * 8 + t1b] * ubr[t0];
    }
    (void)ua; (void)ubr;
    sp[tid] = p0;
    sp[tid + 256] = p1;
    __syncthreads();

    {   // squared norm: warp w handles t1 = w
        int w = tid >> 5, lane = tid & 31;
        float q0 = sp[w * 64 + lane], q1 = sp[w * 64 + 32 + lane];
        float s = q0 * q0 + q1 * q1;
        #pragma unroll
        for (int off = 16; off; off >>= 1) s += __shfl_xor_sync(0xffffffffu, s, off);
        if (lane == 0) sn2[w] = s;
    }
    __syncthreads();

    float na = sn2[t1a], fa = na / ((1.f + na) * sqrtf(na + 1e-9f));
    float nb = sn2[t1b], fb = nb / ((1.f + nb) * sqrtf(nb + 1e-9f));
    float v0 = p0 * fa, v1 = p1 * fb;

    if (iter == 2) {   // coalesced pixel-major scratch; transposed later
        g_v[(size_t)pix * OC_ + tid]       = v0;
        g_v[(size_t)pix * OC_ + tid + 256] = v1;
        return;
    }
    sv[tid] = v0;
    sv[tid + 256] = v1;
    __syncthreads();

    {   // agreement: pair = t0*8+t1 handled by 4 threads (z quarters)
        int pair = tid >> 2, q = tid & 3;
        int t1 = pair & 7;
        float d = 0.f;
        #pragma unroll
        for (int i = 0; i < 16; ++i) {
            int z = q * 16 + ((i + pair) & 15);
            d += su[pair * 64 + z] * sv[t1 * 64 + z];
        }
        d += __shfl_down_sync(0xffffffffu, d, 2, 4);
        d += __shfl_down_sync(0xffffffffu, d, 1, 4);
        if (q == 0) {
            float bold = (iter == 0) ? 0.f : g_b[(n * 64 + pair) * NPIX + hw];
            g_b[(n * 64 + pair) * NPIX + hw] = bold + d;
        }
    }
}

// ---- transpose g_v [n][hw][c] -> out [n][c][hw] ----
__global__ __launch_bounds__(256) void vtrans_kernel(float* __restrict__ out) {
    __shared__ float t[32][33];
    const int n   = blockIdx.z;
    const int hw0 = blockIdx.x * 32;
    const int c0  = blockIdx.y * 32;
    const int x = threadIdx.x & 31, y = threadIdx.x >> 5;
    #pragma unroll
    for (int yy = y; yy < 32; yy += 8)
        t[yy][x] = g_v[((size_t)n * NPIX + hw0 + yy) * OC_ + c0 + x];
    __syncthreads();
    #pragma unroll
    for (int yy = y; yy < 32; yy += 8)
        out[((size_t)n * OC_ + c0 + yy) * NPIX + hw0 + x] = t[x][yy];
}

extern "C" void kernel_launch(void* const* d_in, const int* in_sizes, int n_in,
                              void* d_out, int out_size) {
    const float* x    = (const float*)d_in[0];
    const float* W    = (const float*)d_in[1];
    const float* bias = (const float*)d_in[2];
    float* out = (float*)d_out;

    cudaFuncSetAttribute(conv_mma_kernel,
                         cudaFuncAttributeMaxDynamicSharedMemorySize, SMEMTOT);

    xsplit_kernel<<<dim3(NIMG, HIN), 256>>>(x);
    wsplit_kernel<<<(OC_ * KTOT + 255) / 256, 256>>>(W);
    conv_mma_kernel<<<dim3(8, 4, NIMG), 256, SMEMTOT>>>(bias);
    route_kernel<<<NB * NPIX, 256>>>(0);
    pool_kernel<<<(NB * 64 * NPIX + 255) / 256, 256>>>();
    route_kernel<<<NB * NPIX, 256>>>(1);
    pool_kernel<<<(NB * 64 * NPIX + 255) / 256, 256>>>();
    route_kernel<<<NB * NPIX, 256>>>(2);
    vtrans_kernel<<<dim3(32, 16, NB), 256>>>(out);
}

// round 5
// speedup vs baseline: 2.8932x; 1.3343x over previous
#include <cuda_runtime.h>
#include <cuda_fp16.h>
#include <cstdint>

// CapsuleLayer: conv(stride2,pad1, 32ic->512oc) per (n,t0) image via mma.sync
// fp16 2-term implicit GEMM (A=fp16(x); B=1024*W split hi/lo fp16, epilogue /1024),
// then 3 routing rounds with register-resident u and fused 3x3 maxpool.
// Shapes: x[8,8,32,64,64], W[512,32,3,3], bias[512] -> v[8,8,64,32,32] (fp32)

#define NB   8
#define T0_  8
#define Z0_  32
#define HIN  64
#define WIN  64
#define OC_  512
#define H1_  32
#define W1_  32
#define NPIX (H1_*W1_)      // 1024
#define KTOT 288            // 9 taps * 32 ic
#define NIMG 64
#define WSCALE 1024.0f
#define INV_WSCALE (1.0f/1024.0f)

// ---- device scratch ----
__device__ float  g_uhat[NB*NPIX*T0_*OC_];   // [n][hw][t0][oc]
__device__ float  g_v[NB*NPIX*OC_];          // [n][hw][t1*64+z]
__device__ __half g_xh[NIMG*HIN*WIN*Z0_];    // [img][h][w][ic]  fp16(x)
__device__ __half g_whi[OC_*KTOT];           // [oc][tap*32+ic]  fp16(1024W)
__device__ __half g_wlo[OC_*KTOT];           // residual
__device__ float  g_b[NB*NPIX*64];           // [n][hw][t0*8+t1] routing logits

__device__ __forceinline__ uint32_t smem_u32(const void* p) {
    uint32_t a;
    asm("{ .reg .u64 t; cvta.to.shared.u64 t, %1; cvt.u32.u64 %0, t; }"
        : "=r"(a) : "l"(p));
    return a;
}
__device__ __forceinline__ void ldm_x4(uint32_t* r, uint32_t addr) {
    asm volatile("ldmatrix.sync.aligned.m8n8.x4.shared.b16 {%0,%1,%2,%3}, [%4];"
                 : "=r"(r[0]), "=r"(r[1]), "=r"(r[2]), "=r"(r[3]) : "r"(addr));
}
__device__ __forceinline__ void mma16816(float* d, const uint32_t* a,
                                         uint32_t b0, uint32_t b1) {
    asm volatile(
        "mma.sync.aligned.m16n8k16.row.col.f32.f16.f16.f32 "
        "{%0,%1,%2,%3}, {%4,%5,%6,%7}, {%8,%9}, {%0,%1,%2,%3};"
        : "+f"(d[0]), "+f"(d[1]), "+f"(d[2]), "+f"(d[3])
        : "r"(a[0]), "r"(a[1]), "r"(a[2]), "r"(a[3]), "r"(b0), "r"(b1));
}
__device__ __forceinline__ void cp16(uint32_t d, const void* s, uint32_t n) {
    asm volatile("cp.async.cg.shared.global [%0], [%1], 16, %2;"
                 :: "r"(d), "l"(s), "r"(n) : "memory");
}
__device__ __forceinline__ void cp_commit() {
    asm volatile("cp.async.commit_group;" ::: "memory");
}

// ========================= prep =============================================
__global__ __launch_bounds__(256) void xsplit_kernel(const float* __restrict__ x) {
    __shared__ float t[32][65];
    const int img = blockIdx.x;
    const int h   = blockIdx.y;
    const int tid = threadIdx.x;
    #pragma unroll
    for (int j = 0; j < 8; ++j) {
        int idx = tid + 256 * j;
        int ic = idx >> 6, w = idx & 63;
        t[ic][w] = x[((img * Z0_ + ic) * HIN + h) * WIN + w];
    }
    __syncthreads();
    #pragma unroll
    for (int j = 0; j < 8; ++j) {
        int idx = tid + 256 * j;
        int w = idx >> 5, ic = idx & 31;
        g_xh[((img * HIN + h) * WIN + w) * Z0_ + ic] = __float2half(t[ic][w]);
    }
}

__global__ void wsplit_kernel(const float* __restrict__ W) {
    int idx = blockIdx.x * 256 + threadIdx.x;
    if (idx >= OC_ * KTOT) return;
    int oc = idx / KTOT;
    int k  = idx - oc * KTOT;
    int tap = k >> 5, ic = k & 31;
    float v = W[oc * KTOT + ic * 9 + tap] * WSCALE;
    __half hi = __float2half(v);
    g_whi[idx] = hi;
    g_wlo[idx] = __float2half(v - __half2float(hi));
}

// ========================= conv: mma.sync implicit GEMM =====================
// CTA = 128 px x 128 oc of one image; 8 warps = 4(m) x 2(n); warp = 32px x 64oc.
// K = 9 chunks of 32 (1 tap x 32 ic), cp.async double-buffered.
// Operands per stage: A(fp16 x), Bhi, Blo.
#define APITCH  80
#define OPBYTES (128 * APITCH)     // 10240 per operand
#define STGB    (3 * OPBYTES)      // A, Bhi, Blo = 30720
#define SMEMTOT (2 * STGB)         // 61440

__device__ __forceinline__ void stage_chunk(
        int c, uint32_t sbase, uint32_t dA, int oh, int ow,
        const __half* xImg, const __half* wH, const __half* wL) {
    int kh = c / 3, kw = c - 3 * kh;
    int ih = 2 * oh - 1 + kh, iw = 2 * ow - 1 + kw;
    bool valid = ((unsigned)ih < (unsigned)HIN) && ((unsigned)iw < (unsigned)WIN);
    uint32_t vb = valid ? 16u : 0u;
    size_t so = valid ? (size_t)(ih * WIN + iw) * Z0_ : 0;
    const char* aH = (const char*)(xImg + so);
    cp16(sbase + dA,      aH,      vb);
    cp16(sbase + dA + 16, aH + 16, vb);
    const char* bH = (const char*)(wH + c * 32);
    const char* bL = (const char*)(wL + c * 32);
    cp16(sbase + OPBYTES + dA,          bH,      16u);
    cp16(sbase + OPBYTES + dA + 16,     bH + 16, 16u);
    cp16(sbase + 2 * OPBYTES + dA,      bL,      16u);
    cp16(sbase + 2 * OPBYTES + dA + 16, bL + 16, 16u);
    cp_commit();
}

__device__ __forceinline__ void compute_chunk(
        uint32_t sbase, uint32_t aLane, uint32_t bLane, float acc[2][8][4]) {
    const uint32_t aB   = sbase;
    const uint32_t bHiB = sbase + OPBYTES;
    const uint32_t bLoB = sbase + 2 * OPBYTES;
    #pragma unroll
    for (int ks = 0; ks < 2; ++ks) {
        uint32_t A[2][4];
        #pragma unroll
        for (int i = 0; i < 2; ++i)
            ldm_x4(A[i], aB + i * (16 * APITCH) + ks * 32 + aLane);
        #pragma unroll
        for (int j = 0; j < 4; ++j) {
            uint32_t off = j * (16 * APITCH) + ks * 32 + bLane;
            uint32_t Bhi[4], Blo[4];
            ldm_x4(Bhi, bHiB + off);
            ldm_x4(Blo, bLoB + off);
            #pragma unroll
            for (int i = 0; i < 2; ++i) {
                mma16816(acc[i][2 * j],     A[i], Bhi[0], Bhi[1]);
                mma16816(acc[i][2 * j + 1], A[i], Bhi[2], Bhi[3]);
                mma16816(acc[i][2 * j],     A[i], Blo[0], Blo[1]);
                mma16816(acc[i][2 * j + 1], A[i], Blo[2], Blo[3]);
            }
        }
    }
}

__global__ __launch_bounds__(256, 2) void conv_mma_kernel(const float* __restrict__ bias) {
    extern __shared__ char smem[];
    const uint32_t base0 = smem_u32(smem);
    const uint32_t base1 = base0 + STGB;

    const int tid  = threadIdx.x;
    const int lid  = tid & 31;
    const int wid  = tid >> 5;
    const int mblk = blockIdx.x;   // 0..7 (128-pixel slab)
    const int nblk = blockIdx.y;   // 0..3 (128-oc slab)
    const int img  = blockIdx.z;   // 0..63

    const int warp_m = wid & 3;
    const int warp_n = wid >> 2;
    const int wPx = warp_m * 32;
    const int wOc = warp_n * 64;

    const int p_loc = tid >> 1;
    const int half  = tid & 1;
    const int p     = mblk * 128 + p_loc;
    const int oh = p >> 5, ow = p & 31;
    const uint32_t dA = (uint32_t)(p_loc * APITCH + half * 32);
    const __half* xImg = g_xh + (size_t)img * (HIN * WIN * Z0_) + half * 16;
    const __half* wH = g_whi + (size_t)(nblk * 128 + p_loc) * KTOT + half * 16;
    const __half* wL = g_wlo + (size_t)(nblk * 128 + p_loc) * KTOT + half * 16;

    const uint32_t aRow  = ((lid >> 3) & 1) * 8 + (lid & 7);
    const uint32_t aKoff = (lid >> 4) * 16;
    const uint32_t aLane = (wPx + aRow) * APITCH + aKoff;
    const uint32_t bRow  = (lid >> 4) * 8 + (lid & 7);
    const uint32_t bKoff = ((lid >> 3) & 1) * 16;
    const uint32_t bLane = (wOc + bRow) * APITCH + bKoff;

    float acc[2][8][4];
    #pragma unroll
    for (int i = 0; i < 2; ++i)
        #pragma unroll
        for (int j = 0; j < 8; ++j)
            #pragma unroll
            for (int q = 0; q < 4; ++q) acc[i][j][q] = 0.f;

    stage_chunk(0, base0, dA, oh, ow, xImg, wH, wL);
    stage_chunk(1, base1, dA, oh, ow, xImg, wH, wL);

    #pragma unroll
    for (int c = 0; c < 9; ++c) {
        if (c < 8) asm volatile("cp.async.wait_group 1;" ::: "memory");
        else       asm volatile("cp.async.wait_group 0;" ::: "memory");
        __syncthreads();
        compute_chunk((c & 1) ? base1 : base0, aLane, bLane, acc);
        if (c + 2 < 9) {
            __syncthreads();
            stage_chunk(c + 2, (c & 1) ? base1 : base0, dA, oh, ow, xImg, wH, wL);
        }
    }

    // ---- epilogue: acc/1024 + bias, write pixel-major u_hat ----
    const int n = img >> 3, t0 = img & 7;
    const int rowBase = mblk * 128 + wPx + (lid >> 2);
    const int ocBase  = nblk * 128 + wOc + 2 * (lid & 3);
    #pragma unroll
    for (int j = 0; j < 8; ++j) {
        int oc = ocBase + j * 8;
        float2 bb = *(const float2*)(bias + oc);
        #pragma unroll
        for (int i = 0; i < 2; ++i) {
            int r0 = rowBase + i * 16;
            float* d0 = g_uhat + ((size_t)((n * NPIX + r0) * T0_ + t0)) * OC_ + oc;
            float* d1 = g_uhat + ((size_t)((n * NPIX + r0 + 8) * T0_ + t0)) * OC_ + oc;
            *(float2*)d0 = make_float2(acc[i][j][0] * INV_WSCALE + bb.x,
                                       acc[i][j][1] * INV_WSCALE + bb.y);
            *(float2*)d1 = make_float2(acc[i][j][2] * INV_WSCALE + bb.x,
                                       acc[i][j][3] * INV_WSCALE + bb.y);
        }
    }
}

// ========================= routing ==========================================
// One block per pixel; u kept in registers (thread owns (t1a,za) and (t1b,za)).
// Fused 3x3 maxpool on b (layout [n][hw][64], coalesced).
__global__ __launch_bounds__(256) void route_kernel(int iter) {
    __shared__ float sr[64];           // softmax routing weights
    __shared__ float sbp[64];          // pooled logits
    __shared__ float ns[8][2];         // per-warp partial norms
    __shared__ float part[8][8];       // agreement partials (t1a set)
    __shared__ float part2[8][8];      // agreement partials (t1b set)

    const int pix = blockIdx.x;
    const int n   = pix >> 10;
    const int hw  = pix & 1023;
    const int tid = threadIdx.x;
    const int t1a = tid >> 6, za = tid & 63;
    const int w   = tid >> 5, lane = tid & 31;

    const float* up = g_uhat + (size_t)pix * 4096;
    float ua[8], ub[8];
    #pragma unroll
    for (int t0 = 0; t0 < 8; ++t0) {
        ua[t0] = up[(t0 * 8 + t1a) * 64 + za];
        ub[t0] = up[(t0 * 8 + t1a + 4) * 64 + za];
    }

    if (iter > 0) {
        if (tid < 64) {    // fused 3x3 maxpool over spatial neighbors
            int h = hw >> 5, ww = hw & 31;
            float m = -3.402823466e38f;
            #pragma unroll
            for (int dh = -1; dh <= 1; ++dh) {
                int hh = h + dh;
                if ((unsigned)hh >= (unsigned)H1_) continue;
                #pragma unroll
                for (int dw = -1; dw <= 1; ++dw) {
                    int w2 = ww + dw;
                    if ((unsigned)w2 >= (unsigned)W1_) continue;
                    m = fmaxf(m, g_b[((size_t)n * NPIX + hh * W1_ + w2) * 64 + tid]);
                }
            }
            sbp[tid] = m;
        }
        __syncthreads();
        if (tid < 8) {     // softmax over t1 for t0 = tid
            float m = -1e30f;
            #pragma unroll
            for (int t = 0; t < 8; ++t) m = fmaxf(m, sbp[tid * 8 + t]);
            float e[8], s = 0.f;
            #pragma unroll
            for (int t = 0; t < 8; ++t) { e[t] = expf(sbp[tid * 8 + t] - m); s += e[t]; }
            float inv = 1.f / s;
            #pragma unroll
            for (int t = 0; t < 8; ++t) sr[tid * 8 + t] = e[t] * inv;
        }
        __syncthreads();
    }

    float p0 = 0.f, p1 = 0.f;
    if (iter > 0) {
        #pragma unroll
        for (int t0 = 0; t0 < 8; ++t0) {
            p0 += sr[t0 * 8 + t1a] * ua[t0];
            p1 += sr[t0 * 8 + t1a + 4] * ub[t0];
        }
    } else {
        #pragma unroll
        for (int t0 = 0; t0 < 8; ++t0) { p0 += ua[t0]; p1 += ub[t0]; }
        p0 *= 0.125f;
        p1 *= 0.125f;
    }

    // squared norms per t1 (64 threads = 2 warps per t1 group)
    float s0 = p0 * p0, s1 = p1 * p1;
    #pragma unroll
    for (int off = 16; off; off >>= 1) {
        s0 += __shfl_xor_sync(0xffffffffu, s0, off);
        s1 += __shfl_xor_sync(0xffffffffu, s1, off);
    }
    if (lane == 0) { ns[w][0] = s0; ns[w][1] = s1; }
    __syncthreads();

    float na = ns[2 * t1a][0] + ns[2 * t1a + 1][0];
    float nb = ns[2 * t1a][1] + ns[2 * t1a + 1][1];
    float fa = na / ((1.f + na) * sqrtf(na + 1e-9f));
    float fb = nb / ((1.f + nb) * sqrtf(nb + 1e-9f));
    float v0 = p0 * fa, v1 = p1 * fb;

    if (iter == 2) {      // coalesced pixel-major scratch; transposed later
        g_v[(size_t)pix * OC_ + tid]       = v0;
        g_v[(size_t)pix * OC_ + tid + 256] = v1;
        return;
    }

    // agreement: b[t0][t1] += sum_z u[t0][t1][z]*v[t1][z]; thread owns u and v
    #pragma unroll
    for (int t0 = 0; t0 < 8; ++t0) {
        float da = ua[t0] * v0;
        float db = ub[t0] * v1;
        #pragma unroll
        for (int off = 16; off; off >>= 1) {
            da += __shfl_xor_sync(0xffffffffu, da, off);
            db += __shfl_xor_sync(0xffffffffu, db, off);
        }
        if (lane == 0) { part[w][t0] = da; part2[w][t0] = db; }
    }
    __syncthreads();

    if (tid < 64) {
        int t0 = tid >> 3, t1 = tid & 7;
        float d = (t1 < 4)
            ? part[2 * t1][t0] + part[2 * t1 + 1][t0]
            : part2[2 * (t1 - 4)][t0] + part2[2 * (t1 - 4) + 1][t0];
        float bold = (iter == 0) ? 0.f
                     : g_b[((size_t)n * NPIX + hw) * 64 + tid];
        g_b[((size_t)n * NPIX + hw) * 64 + tid] = bold + d;
    }
}

// ---- transpose g_v [n][hw][c] -> out [n][c][hw] ----
__global__ __launch_bounds__(256) void vtrans_kernel(float* __restrict__ out) {
    __shared__ float t[32][33];
    const int n   = blockIdx.z;
    const int hw0 = blockIdx.x * 32;
    const int c0  = blockIdx.y * 32;
    const int x = threadIdx.x & 31, y = threadIdx.x >> 5;
    #pragma unroll
    for (int yy = y; yy < 32; yy += 8)
        t[yy][x] = g_v[((size_t)n * NPIX + hw0 + yy) * OC_ + c0 + x];
    __syncthreads();
    #pragma unroll
    for (int yy = y; yy < 32; yy += 8)
        out[((size_t)n * OC_ + c0 + yy) * NPIX + hw0 + x] = t[x][yy];
}

extern "C" void kernel_launch(void* const* d_in, const int* in_sizes, int n_in,
                              void* d_out, int out_size) {
    const float* x    = (const float*)d_in[0];
    const float* W    = (const float*)d_in[1];
    const float* bias = (const float*)d_in[2];
    float* out = (float*)d_out;

    cudaFuncSetAttribute(conv_mma_kernel,
                         cudaFuncAttributeMaxDynamicSharedMemorySize, SMEMTOT);

    xsplit_kernel<<<dim3(NIMG, HIN), 256>>>(x);
    wsplit_kernel<<<(OC_ * KTOT + 255) / 256, 256>>>(W);
    conv_mma_kernel<<<dim3(8, 4, NIMG), 256, SMEMTOT>>>(bias);
    route_kernel<<<NB * NPIX, 256>>>(0);
    route_kernel<<<NB * NPIX, 256>>>(1);
    route_kernel<<<NB * NPIX, 256>>>(2);
    vtrans_kernel<<<dim3(32, 16, NB), 256>>>(out);
}

// round 7
// speedup vs baseline: 3.2399x; 1.1198x over previous
#include <cuda_runtime.h>
#include <cuda_fp16.h>
#include <cstdint>

// CapsuleLayer: conv(stride2,pad1, 32ic->512oc) per (n,t0) image via mma.sync
// fp16 2-term implicit GEMM (A=fp16(x); B=1024*W split hi/lo fp16, epilogue /1024),
// 3-stage cp.async pipeline. Then 3 routing rounds with float4 register-resident
// u, fused 3x3 maxpool, and PING-PONG b buffers (race-free across blocks).
// Shapes: x[8,8,32,64,64], W[512,32,3,3], bias[512] -> v[8,8,64,32,32] (fp32)

#define NB   8
#define T0_  8
#define Z0_  32
#define HIN  64
#define WIN  64
#define OC_  512
#define H1_  32
#define W1_  32
#define NPIX (H1_*W1_)      // 1024
#define KTOT 288            // 9 taps * 32 ic
#define NIMG 64
#define WSCALE 1024.0f
#define INV_WSCALE (1.0f/1024.0f)

// ---- device scratch ----
__device__ float  g_uhat[NB*NPIX*T0_*OC_];   // [n][hw][t0][oc]
__device__ float  g_v[NB*NPIX*OC_];          // [n][hw][t1*64+z]
__device__ __half g_xh[NIMG*HIN*WIN*Z0_];    // [img][h][w][ic]  fp16(x)
__device__ __half g_whi[OC_*KTOT];           // [oc][tap*32+ic]  fp16(1024W)
__device__ __half g_wlo[OC_*KTOT];           // residual
__device__ float  g_bA[NB*NPIX*64];          // routing logits after iter0
__device__ float  g_bB[NB*NPIX*64];          // routing logits after iter1

__device__ __forceinline__ uint32_t smem_u32(const void* p) {
    uint32_t a;
    asm("{ .reg .u64 t; cvta.to.shared.u64 t, %1; cvt.u32.u64 %0, t; }"
        : "=r"(a) : "l"(p));
    return a;
}
__device__ __forceinline__ void ldm_x4(uint32_t* r, uint32_t addr) {
    asm volatile("ldmatrix.sync.aligned.m8n8.x4.shared.b16 {%0,%1,%2,%3}, [%4];"
                 : "=r"(r[0]), "=r"(r[1]), "=r"(r[2]), "=r"(r[3]) : "r"(addr));
}
__device__ __forceinline__ void mma16816(float* d, const uint32_t* a,
                                         uint32_t b0, uint32_t b1) {
    asm volatile(
        "mma.sync.aligned.m16n8k16.row.col.f32.f16.f16.f32 "
        "{%0,%1,%2,%3}, {%4,%5,%6,%7}, {%8,%9}, {%0,%1,%2,%3};"
        : "+f"(d[0]), "+f"(d[1]), "+f"(d[2]), "+f"(d[3])
        : "r"(a[0]), "r"(a[1]), "r"(a[2]), "r"(a[3]), "r"(b0), "r"(b1));
}
__device__ __forceinline__ void cp16(uint32_t d, const void* s, uint32_t n) {
    asm volatile("cp.async.cg.shared.global [%0], [%1], 16, %2;"
                 :: "r"(d), "l"(s), "r"(n) : "memory");
}
__device__ __forceinline__ void cp_commit() {
    asm volatile("cp.async.commit_group;" ::: "memory");
}

// ========================= prep =============================================
__global__ __launch_bounds__(256) void xsplit_kernel(const float* __restrict__ x) {
    __shared__ float t[32][65];
    const int img = blockIdx.x;
    const int h   = blockIdx.y;
    const int tid = threadIdx.x;
    #pragma unroll
    for (int j = 0; j < 8; ++j) {
        int idx = tid + 256 * j;
        int ic = idx >> 6, w = idx & 63;
        t[ic][w] = x[((img * Z0_ + ic) * HIN + h) * WIN + w];
    }
    __syncthreads();
    #pragma unroll
    for (int j = 0; j < 8; ++j) {
        int idx = tid + 256 * j;
        int w = idx >> 5, ic = idx & 31;
        g_xh[((img * HIN + h) * WIN + w) * Z0_ + ic] = __float2half(t[ic][w]);
    }
}

__global__ void wsplit_kernel(const float* __restrict__ W) {
    int idx = blockIdx.x * 256 + threadIdx.x;
    if (idx >= OC_ * KTOT) return;
    int oc = idx / KTOT;
    int k  = idx - oc * KTOT;
    int tap = k >> 5, ic = k & 31;
    float v = W[oc * KTOT + ic * 9 + tap] * WSCALE;
    __half hi = __float2half(v);
    g_whi[idx] = hi;
    g_wlo[idx] = __float2half(v - __half2float(hi));
}

// ========================= conv: mma.sync implicit GEMM =====================
// CTA = 128 px x 128 oc of one image; 8 warps = 4(m) x 2(n); warp = 32px x 64oc.
// K = 9 chunks of 32 (1 tap x 32 ic), cp.async 3-stage pipeline, 1 sync/chunk.
#define APITCH  80
#define OPBYTES (128 * APITCH)     // 10240 per operand
#define STGB    (3 * OPBYTES)      // A, Bhi, Blo = 30720
#define SMEMTOT (3 * STGB)         // 92160 (3 stages)

__device__ __forceinline__ void stage_chunk(
        int c, uint32_t sbase, uint32_t dA, int oh, int ow,
        const __half* xImg, const __half* wH, const __half* wL) {
    int kh = c / 3, kw = c - 3 * kh;
    int ih = 2 * oh - 1 + kh, iw = 2 * ow - 1 + kw;
    bool valid = ((unsigned)ih < (unsigned)HIN) && ((unsigned)iw < (unsigned)WIN);
    uint32_t vb = valid ? 16u : 0u;
    size_t so = valid ? (size_t)(ih * WIN + iw) * Z0_ : 0;
    const char* aH = (const char*)(xImg + so);
    cp16(sbase + dA,      aH,      vb);
    cp16(sbase + dA + 16, aH + 16, vb);
    const char* bH = (const char*)(wH + c * 32);
    const char* bL = (const char*)(wL + c * 32);
    cp16(sbase + OPBYTES + dA,          bH,      16u);
    cp16(sbase + OPBYTES + dA + 16,     bH + 16, 16u);
    cp16(sbase + 2 * OPBYTES + dA,      bL,      16u);
    cp16(sbase + 2 * OPBYTES + dA + 16, bL + 16, 16u);
    cp_commit();
}

__device__ __forceinline__ void compute_chunk(
        uint32_t sbase, uint32_t aLane, uint32_t bLane, float acc[2][8][4]) {
    const uint32_t aB   = sbase;
    const uint32_t bHiB = sbase + OPBYTES;
    const uint32_t bLoB = sbase + 2 * OPBYTES;
    #pragma unroll
    for (int ks = 0; ks < 2; ++ks) {
        uint32_t A[2][4];
        #pragma unroll
        for (int i = 0; i < 2; ++i)
            ldm_x4(A[i], aB + i * (16 * APITCH) + ks * 32 + aLane);
        #pragma unroll
        for (int j = 0; j < 4; ++j) {
            uint32_t off = j * (16 * APITCH) + ks * 32 + bLane;
            uint32_t Bhi[4], Blo[4];
            ldm_x4(Bhi, bHiB + off);
            ldm_x4(Blo, bLoB + off);
            #pragma unroll
            for (int i = 0; i < 2; ++i) {
                mma16816(acc[i][2 * j],     A[i], Bhi[0], Bhi[1]);
                mma16816(acc[i][2 * j + 1], A[i], Bhi[2], Bhi[3]);
                mma16816(acc[i][2 * j],     A[i], Blo[0], Blo[1]);
                mma16816(acc[i][2 * j + 1], A[i], Blo[2], Blo[3]);
            }
        }
    }
}

__global__ __launch_bounds__(256, 2) void conv_mma_kernel(const float* __restrict__ bias) {
    extern __shared__ char smem[];
    const uint32_t sbase0 = smem_u32(smem);

    const int tid  = threadIdx.x;
    const int lid  = tid & 31;
    const int wid  = tid >> 5;
    const int mblk = blockIdx.x;   // 0..7 (128-pixel slab)
    const int nblk = blockIdx.y;   // 0..3 (128-oc slab)
    const int img  = blockIdx.z;   // 0..63

    const int warp_m = wid & 3;
    const int warp_n = wid >> 2;
    const int wPx = warp_m * 32;
    const int wOc = warp_n * 64;

    const int p_loc = tid >> 1;
    const int half  = tid & 1;
    const int p     = mblk * 128 + p_loc;
    const int oh = p >> 5, ow = p & 31;
    const uint32_t dA = (uint32_t)(p_loc * APITCH + half * 32);
    const __half* xImg = g_xh + (size_t)img * (HIN * WIN * Z0_) + half * 16;
    const __half* wH = g_whi + (size_t)(nblk * 128 + p_loc) * KTOT + half * 16;
    const __half* wL = g_wlo + (size_t)(nblk * 128 + p_loc) * KTOT + half * 16;

    const uint32_t aRow  = ((lid >> 3) & 1) * 8 + (lid & 7);
    const uint32_t aKoff = (lid >> 4) * 16;
    const uint32_t aLane = (wPx + aRow) * APITCH + aKoff;
    const uint32_t bRow  = (lid >> 4) * 8 + (lid & 7);
    const uint32_t bKoff = ((lid >> 3) & 1) * 16;
    const uint32_t bLane = (wOc + bRow) * APITCH + bKoff;

    float acc[2][8][4];
    #pragma unroll
    for (int i = 0; i < 2; ++i)
        #pragma unroll
        for (int j = 0; j < 8; ++j)
            #pragma unroll
            for (int q = 0; q < 4; ++q) acc[i][j][q] = 0.f;

    stage_chunk(0, sbase0,        dA, oh, ow, xImg, wH, wL);
    stage_chunk(1, sbase0 + STGB, dA, oh, ow, xImg, wH, wL);

    #pragma unroll
    for (int c = 0; c < 9; ++c) {
        if (c < 7) asm volatile("cp.async.wait_group 1;" ::: "memory");
        else       asm volatile("cp.async.wait_group 0;" ::: "memory");
        __syncthreads();
        if (c + 2 < 9)   // buffer (c+2)%3 last read in iteration c-1 (sync'd)
            stage_chunk(c + 2, sbase0 + ((c + 2) % 3) * STGB, dA, oh, ow,
                        xImg, wH, wL);
        compute_chunk(sbase0 + (c % 3) * STGB, aLane, bLane, acc);
    }

    // ---- epilogue: acc/1024 + bias, write pixel-major u_hat ----
    const int n = img >> 3, t0 = img & 7;
    const int rowBase = mblk * 128 + wPx + (lid >> 2);
    const int ocBase  = nblk * 128 + wOc + 2 * (lid & 3);
    #pragma unroll
    for (int j = 0; j < 8; ++j) {
        int oc = ocBase + j * 8;
        float2 bb = *(const float2*)(bias + oc);
        #pragma unroll
        for (int i = 0; i < 2; ++i) {
            int r0 = rowBase + i * 16;
            float* d0 = g_uhat + ((size_t)((n * NPIX + r0) * T0_ + t0)) * OC_ + oc;
            float* d1 = g_uhat + ((size_t)((n * NPIX + r0 + 8) * T0_ + t0)) * OC_ + oc;
            *(float2*)d0 = make_float2(acc[i][j][0] * INV_WSCALE + bb.x,
                                       acc[i][j][1] * INV_WSCALE + bb.y);
            *(float2*)d1 = make_float2(acc[i][j][2] * INV_WSCALE + bb.x,
                                       acc[i][j][3] * INV_WSCALE + bb.y);
        }
    }
}

// ========================= routing ==========================================
// One block per pixel. t1 = warp, q = z-quad, halfsel = t0 half; u as 4 float4.
// Ping-pong b: iter0 writes g_bA; iter1 reads g_bA writes g_bB; iter2 reads g_bB.
__global__ __launch_bounds__(256) void route_kernel(int iter) {
    __shared__ float sr[64];           // softmax routing weights
    __shared__ float sbp[64];          // pooled logits

    const int pix = blockIdx.x;
    const int n   = pix >> 10;
    const int hw  = pix & 1023;
    const int tid = threadIdx.x;
    const int t1   = tid >> 5;         // warp id = output capsule
    const int lane = tid & 31;
    const int q    = lane >> 1;        // z-quad 0..15
    const int halfsel = lane & 1;      // t0 in [0..3] or [4..7]
    const int t0b  = halfsel * 4;

    const float* bin = (iter == 1) ? g_bA : g_bB;   // pool source (iter>0)
    float*       bout = (iter == 0) ? g_bA : g_bB;  // agreement target (iter<2)

    const float* up = g_uhat + (size_t)pix * 4096;
    float4 U[4];
    #pragma unroll
    for (int i = 0; i < 4; ++i)
        U[i] = *(const float4*)(up + ((t0b + i) * 8 + t1) * 64 + q * 4);

    if (iter > 0) {
        if (tid < 64) {    // fused 3x3 maxpool over spatial neighbors (read-only)
            int h = hw >> 5, ww = hw & 31;
            float m = -3.402823466e38f;
            #pragma unroll
            for (int dh = -1; dh <= 1; ++dh) {
                int hh = h + dh;
                if ((unsigned)hh >= (unsigned)H1_) continue;
                #pragma unroll
                for (int dw = -1; dw <= 1; ++dw) {
                    int w2 = ww + dw;
                    if ((unsigned)w2 >= (unsigned)W1_) continue;
                    m = fmaxf(m, bin[((size_t)n * NPIX + hh * W1_ + w2) * 64 + tid]);
                }
            }
            sbp[tid] = m;
        }
        __syncthreads();
        if (tid < 8) {     // softmax over t1 for t0 = tid
            float m = -1e30f;
            #pragma unroll
            for (int t = 0; t < 8; ++t) m = fmaxf(m, sbp[tid * 8 + t]);
            float e[8], s = 0.f;
            #pragma unroll
            for (int t = 0; t < 8; ++t) { e[t] = expf(sbp[tid * 8 + t] - m); s += e[t]; }
            float inv = 1.f / s;
            #pragma unroll
            for (int t = 0; t < 8; ++t) sr[tid * 8 + t] = e[t] * inv;
        }
        __syncthreads();
    }

    // p for the 4 owned z values (half-sum over 4 t0 + partner shuffle)
    float p4[4];
    if (iter > 0) {
        float r[4];
        #pragma unroll
        for (int i = 0; i < 4; ++i) r[i] = sr[(t0b + i) * 8 + t1];
        #pragma unroll
        for (int j = 0; j < 4; ++j)
            p4[j] = r[0] * (&U[0].x)[j] + r[1] * (&U[1].x)[j]
                  + r[2] * (&U[2].x)[j] + r[3] * (&U[3].x)[j];
    } else {
        #pragma unroll
        for (int j = 0; j < 4; ++j)
            p4[j] = 0.125f * ((&U[0].x)[j] + (&U[1].x)[j]
                            + (&U[2].x)[j] + (&U[3].x)[j]);
    }
    #pragma unroll
    for (int j = 0; j < 4; ++j)
        p4[j] += __shfl_xor_sync(0xffffffffu, p4[j], 1);

    // squared norm for this t1: warp sum (each quad present on 2 lanes -> x0.5)
    float s2 = p4[0] * p4[0] + p4[1] * p4[1] + p4[2] * p4[2] + p4[3] * p4[3];
    #pragma unroll
    for (int off = 16; off; off >>= 1)
        s2 += __shfl_xor_sync(0xffffffffu, s2, off);
    float nn = 0.5f * s2;
    float f = nn / ((1.f + nn) * sqrtf(nn + 1e-9f));

    float v4[4];
    #pragma unroll
    for (int j = 0; j < 4; ++j) v4[j] = p4[j] * f;

    if (iter == 2) {      // coalesced pixel-major scratch; transposed later
        if (halfsel == 0)
            *(float4*)(g_v + (size_t)pix * OC_ + t1 * 64 + q * 4) =
                make_float4(v4[0], v4[1], v4[2], v4[3]);
        return;
    }

    // agreement: bout[t0][t1] = bin_cum + sum_z u*v (thread has u 4t0 x 4z, v 4z)
    float da[4];
    #pragma unroll
    for (int i = 0; i < 4; ++i)
        da[i] = (&U[i].x)[0] * v4[0] + (&U[i].x)[1] * v4[1]
              + (&U[i].x)[2] * v4[2] + (&U[i].x)[3] * v4[3];
    #pragma unroll
    for (int off = 2; off <= 16; off <<= 1)
        #pragma unroll
        for (int i = 0; i < 4; ++i)
            da[i] += __shfl_xor_sync(0xffffffffu, da[i], off);

    if (lane < 2) {       // lane0: t0=0..3, lane1: t0=4..7
        const float* bcum = g_bA + ((size_t)n * NPIX + hw) * 64;
        float* bo = bout + ((size_t)n * NPIX + hw) * 64;
        #pragma unroll
        for (int i = 0; i < 4; ++i) {
            int c = (t0b + i) * 8 + t1;
            float bold = (iter == 0) ? 0.f : bcum[c];
            bo[c] = bold + da[i];
        }
    }
}

// ---- transpose g_v [n][hw][c] -> out [n][c][hw] ----
__global__ __launch_bounds__(256) void vtrans_kernel(float* __restrict__ out) {
    __shared__ float t[32][33];
    const int n   = blockIdx.z;
    const int hw0 = blockIdx.x * 32;
    const int c0  = blockIdx.y * 32;
    const int x = threadIdx.x & 31, y = threadIdx.x >> 5;
    #pragma unroll
    for (int yy = y; yy < 32; yy += 8)
        t[yy][x] = g_v[((size_t)n * NPIX + hw0 + yy) * OC_ + c0 + x];
    __syncthreads();
    #pragma unroll
    for (int yy = y; yy < 32; yy += 8)
        out[((size_t)n * OC_ + c0 + yy) * NPIX + hw0 + x] = t[x][yy];
}

extern "C" void kernel_launch(void* const* d_in, const int* in_sizes, int n_in,
                              void* d_out, int out_size) {
    const float* x    = (const float*)d_in[0];
    const float* W    = (const float*)d_in[1];
    const float* bias = (const float*)d_in[2];
    float* out = (float*)d_out;

    cudaFuncSetAttribute(conv_mma_kernel,
                         cudaFuncAttributeMaxDynamicSharedMemorySize, SMEMTOT);

    xsplit_kernel<<<dim3(NIMG, HIN), 256>>>(x);
    wsplit_kernel<<<(OC_ * KTOT + 255) / 256, 256>>>(W);
    conv_mma_kernel<<<dim3(8, 4, NIMG), 256, SMEMTOT>>>(bias);
    route_kernel<<<NB * NPIX, 256>>>(0);
    route_kernel<<<NB * NPIX, 256>>>(1);
    route_kernel<<<NB * NPIX, 256>>>(2);
    vtrans_kernel<<<dim3(32, 16, NB), 256>>>(out);
}